// round 13
// baseline (speedup 1.0000x reference)
#include <cuda_runtime.h>
#include <cuda_bf16.h>
#include <cstdint>

#define HID     128
#define KDIM    256
#define TILE    64
#define THREADS 256
#define NWARP   8
#define KPITCH  264
#define ROWB    (KPITCH * 2)   // 528 B row pitch, 132 words

// ---- SMEM layout (bytes) ----
#define SM_B1   0
#define SM_W2   512
#define SM_RED  1536                           // 64 edges x 4 slices x float2 = 2048
#define SM_WHI  4096
#define SM_WLO  (SM_WHI + HID * ROWB)          // +67584
#define SM_XHI  (SM_WLO + HID * ROWB)          // +67584
#define SM_XLO  (SM_XHI + TILE * ROWB)         // +33792
#define SM_EX   SM_XHI                         // exchange overlays X-hi (32KB <= 33792)
#define SMEM_BYTES (SM_XLO + TILE * ROWB)      // 206848 B

#define MMA_BF16(c, a0, a1, a2, a3, b0, b1) \
    asm volatile("mma.sync.aligned.m16n8k16.row.col.f32.bf16.bf16.f32 " \
        "{%0,%1,%2,%3}, {%4,%5,%6,%7}, {%8,%9}, {%0,%1,%2,%3};" \
        : "+f"((c)[0]), "+f"((c)[1]), "+f"((c)[2]), "+f"((c)[3]) \
        : "r"(a0), "r"(a1), "r"(a2), "r"(a3), "r"(b0), "r"(b1))

#define LDSM_X4(r0, r1, r2, r3, a) \
    asm volatile("ldmatrix.sync.aligned.m8n8.x4.shared.b16 {%0,%1,%2,%3}, [%4];" \
        : "=r"(r0), "=r"(r1), "=r"(r2), "=r"(r3) : "r"(a))
#define LDSM_X2(r0, r1, a) \
    asm volatile("ldmatrix.sync.aligned.m8n8.x2.shared.b16 {%0,%1}, [%2];" \
        : "=r"(r0), "=r"(r1) : "r"(a))

static __device__ __forceinline__ uint32_t smem_u32(const void* p) {
    uint32_t a;
    asm("{ .reg .u64 t; cvta.to.shared.u64 t, %1; cvt.u32.u64 %0, t; }" : "=r"(a) : "l"(p));
    return a;
}
static __device__ __forceinline__ uint32_t packbf(float e0, float e1) {
    union { ushort2 s; uint32_t u; } u;
    u.s.x = __bfloat16_as_ushort(__float2bfloat16(e0));
    u.s.y = __bfloat16_as_ushort(__float2bfloat16(e1));
    return u.u;
}
static __device__ __forceinline__ float bfres(float x) {
    return x - __bfloat162float(__float2bfloat16(x));
}

__global__ void __launch_bounds__(THREADS, 1)
edge_mlp_mma(const float* __restrict__ node_emb,
             const void*  __restrict__ edge_index,
             const float* __restrict__ W1,
             const float* __restrict__ b1,
             const float* __restrict__ W2,
             const float* __restrict__ b2,
             float* __restrict__ out,
             int E)
{
    extern __shared__ char smem[];
    float*  sB1  = (float*)(smem + SM_B1);
    float*  sW2  = (float*)(smem + SM_W2);
    float2* sRed = (float2*)(smem + SM_RED);   // [edge][slice]
    float4* sEx  = (float4*)(smem + SM_EX);    // [slice][mt][j][lane]
    const uint32_t sbase = smem_u32(smem);

    const int tid   = threadIdx.x;
    const int warp  = tid >> 5;
    const int lane  = tid & 31;
    const int g     = lane >> 2;
    const int t     = lane & 3;
    const int slice = warp & 3;     // N-slice: features [slice*32, slice*32+32)
    const int khalf = warp >> 2;    // K-half:  k in [khalf*128, khalf*128+128)

    // ---- one-time staging: b1, W2, W1^T hi/lo ----
    for (int i = tid; i < HID;     i += THREADS) sB1[i] = __ldg(b1 + i);
    for (int i = tid; i < 2 * HID; i += THREADS) sW2[i] = __ldg(W2 + i);
    const float b2x = __ldg(b2), b2y = __ldg(b2 + 1);

    for (int i = tid; i < KDIM * HID; i += THREADS) {
        int k = i >> 7, n = i & 127;           // W1[k][n], coalesced
        float f = __ldg(W1 + i);
        __nv_bfloat16 h = __float2bfloat16(f);
        *(__nv_bfloat16*)(smem + SM_WHI + n * ROWB + k * 2) = h;
        *(__nv_bfloat16*)(smem + SM_WLO + n * ROWB + k * 2) =
            __float2bfloat16(f - __bfloat162float(h));
    }

    // edge_index dtype sniff (int64 idx < 1e5 -> high words zero)
    bool is64 = true;
    const unsigned* uwp = (const unsigned*)edge_index;
    #pragma unroll
    for (int i = 0; i < 16; i++) is64 = is64 && (uwp[2 * i + 1] == 0u);
    const long long* idx64 = (const long long*)edge_index;
    const int*       idx32 = (const int*)edge_index;

    __syncthreads();

    // ---- B-hi fragments resident: this warp's (slice, khalf) block ----
    const uint32_t bRow = (uint32_t)((lane & 7) * ROWB + ((lane >> 3) & 1) * 16);
    uint32_t bh[8][4][2];
    #pragma unroll
    for (int kt = 0; kt < 8; kt++)
        #pragma unroll
        for (int j = 0; j < 4; j++) {
            const uint32_t off = (uint32_t)((slice * 4 + j) * (8 * ROWB)
                                          + (khalf * 8 + kt) * 32);
            LDSM_X2(bh[kt][j][0], bh[kt][j][1], sbase + SM_WHI + bRow + off);
        }

    // A fragment base (row = edge-in-tile)
    const uint32_t aHiB = sbase + SM_XHI + (uint32_t)((lane & 15) * ROWB + (lane >> 4) * 16);
    const uint32_t aLoB = aHiB + (uint32_t)(SM_XLO - SM_XHI);

    const int nTiles = (E + TILE - 1) / TILE;
    float2* out2 = (float2*)out;

    for (int tile = blockIdx.x; tile < nTiles; tile += gridDim.x) {
        const int e0 = tile * TILE;

        __syncthreads();   // prior tile's exchange/sRed reads done

        // ---- gather: one warp per edge-half row, fully coalesced ----
        for (int i = warp; i < 2 * TILE; i += NWARP) {
            const int el = i >> 1, half = i & 1;
            const int e  = e0 + el;
            int node = 0;
            if (lane == 0 && e < E) {
                if (is64) node = (int)idx64[half ? (size_t)E + e : (size_t)e];
                else      node = idx32[half ? (size_t)E + e : (size_t)e];
            }
            node = __shfl_sync(0xffffffffu, node, 0);
            float4 v = __ldg((const float4*)(node_emb + (size_t)node * HID) + lane);
            const int wo = el * (ROWB / 4) + half * 64 + 2 * lane;
            ((uint2*)((uint32_t*)(smem + SM_XHI) + wo))[0] =
                make_uint2(packbf(__bfloat162float(__float2bfloat16(v.x)),
                                  __bfloat162float(__float2bfloat16(v.y))),
                           packbf(__bfloat162float(__float2bfloat16(v.z)),
                                  __bfloat162float(__float2bfloat16(v.w))));
            ((uint2*)((uint32_t*)(smem + SM_XLO) + wo))[0] =
                make_uint2(packbf(bfres(v.x), bfres(v.y)),
                           packbf(bfres(v.z), bfres(v.w)));
        }
        __syncthreads();

        // ---- MMA: acc[mt][j][c], this warp's K-half only ----
        float acc[4][4][4];
        #pragma unroll
        for (int mt = 0; mt < 4; mt++)
            #pragma unroll
            for (int j = 0; j < 4; j++)
                #pragma unroll
                for (int c = 0; c < 4; c++) acc[mt][j][c] = 0.f;

        #pragma unroll
        for (int kt = 0; kt < 8; kt++) {
            const uint32_t kb = (uint32_t)((khalf * 8 + kt) * 32);
            uint32_t bl[4][2];
            #pragma unroll
            for (int j = 0; j < 4; j++)
                LDSM_X2(bl[j][0], bl[j][1],
                        sbase + SM_WLO + bRow
                        + (uint32_t)((slice * 4 + j) * (8 * ROWB)) + kb);
            #pragma unroll
            for (int mt = 0; mt < 4; mt++) {
                uint32_t ah0, ah1, ah2, ah3, al0, al1, al2, al3;
                const uint32_t mo = (uint32_t)(mt * 16 * ROWB) + kb;
                LDSM_X4(ah0, ah1, ah2, ah3, aHiB + mo);
                LDSM_X4(al0, al1, al2, al3, aLoB + mo);
                #pragma unroll
                for (int j = 0; j < 4; j++) {
                    MMA_BF16(acc[mt][j], ah0, ah1, ah2, ah3, bh[kt][j][0], bh[kt][j][1]);
                    MMA_BF16(acc[mt][j], al0, al1, al2, al3, bh[kt][j][0], bh[kt][j][1]);
                    MMA_BF16(acc[mt][j], ah0, ah1, ah2, ah3, bl[j][0], bl[j][1]);
                }
            }
        }
        __syncthreads();   // all LDSM reads of X done (exchange overlays X-hi)

        // ---- split-K exchange: khalf1 stores C-fragments, khalf0 adds ----
        if (khalf == 1) {
            #pragma unroll
            for (int mt = 0; mt < 4; mt++)
                #pragma unroll
                for (int j = 0; j < 4; j++)
                    sEx[((slice * 4 + mt) * 4 + j) * 32 + lane] =
                        make_float4(acc[mt][j][0], acc[mt][j][1],
                                    acc[mt][j][2], acc[mt][j][3]);
        }
        __syncthreads();

        if (khalf == 0) {
            #pragma unroll
            for (int mt = 0; mt < 4; mt++) {
                float p0a = 0.f, p1a = 0.f, p0b = 0.f, p1b = 0.f;
                #pragma unroll
                for (int j = 0; j < 4; j++) {
                    float4 v = sEx[((slice * 4 + mt) * 4 + j) * 32 + lane];
                    acc[mt][j][0] += v.x; acc[mt][j][1] += v.y;
                    acc[mt][j][2] += v.z; acc[mt][j][3] += v.w;
                    #pragma unroll
                    for (int c = 0; c < 2; c++) {
                        const int f = slice * 32 + j * 8 + t * 2 + c;
                        const float w20 = sW2[2 * f], w21 = sW2[2 * f + 1], bb = sB1[f];
                        float ha = fmaxf(acc[mt][j][c]     + bb, 0.f);
                        float hb = fmaxf(acc[mt][j][c + 2] + bb, 0.f);
                        p0a = fmaf(ha, w20, p0a);  p1a = fmaf(ha, w21, p1a);
                        p0b = fmaf(hb, w20, p0b);  p1b = fmaf(hb, w21, p1b);
                    }
                }
                #pragma unroll
                for (int off = 1; off <= 2; off <<= 1) {
                    p0a += __shfl_xor_sync(0xffffffffu, p0a, off);
                    p1a += __shfl_xor_sync(0xffffffffu, p1a, off);
                    p0b += __shfl_xor_sync(0xffffffffu, p0b, off);
                    p1b += __shfl_xor_sync(0xffffffffu, p1b, off);
                }
                if (t == 0) {
                    sRed[(mt * 16 + g)     * 4 + slice] = make_float2(p0a, p1a);
                    sRed[(mt * 16 + g + 8) * 4 + slice] = make_float2(p0b, p1b);
                }
            }
        }
        __syncthreads();

        // ---- final reduce over 4 slices + b2 (done by idle khalf1 threads) ----
        if (tid >= 128 && tid < 128 + TILE) {
            const int el = tid - 128;
            const int e  = e0 + el;
            float2 s = make_float2(b2x, b2y);
            #pragma unroll
            for (int w = 0; w < 4; w++) {
                float2 v = sRed[el * 4 + w];
                s.x += v.x; s.y += v.y;
            }
            if (e < E) out2[e] = s;
        }
    }
}

extern "C" void kernel_launch(void* const* d_in, const int* in_sizes, int n_in,
                              void* d_out, int out_size) {
    const float* node_emb   = (const float*)d_in[0];
    const void*  edge_index = d_in[1];
    const float* W1         = (const float*)d_in[2];
    const float* b1         = (const float*)d_in[3];
    const float* W2         = (const float*)d_in[4];
    const float* b2         = (const float*)d_in[5];
    (void)in_sizes; (void)n_in;

    const int E = out_size / 2;
    const int nTiles = (E + TILE - 1) / TILE;

    cudaFuncSetAttribute(edge_mlp_mma,
                         cudaFuncAttributeMaxDynamicSharedMemorySize, SMEM_BYTES);

    int dev = 0, sms = 148;
    cudaGetDevice(&dev);
    cudaDeviceGetAttribute(&sms, cudaDevAttrMultiProcessorCount, dev);
    int grid = sms < nTiles ? sms : nTiles;

    edge_mlp_mma<<<grid, THREADS, SMEM_BYTES>>>(
        node_emb, edge_index, W1, b1, W2, b2, (float*)d_out, E);
}